// round 11
// baseline (speedup 1.0000x reference)
#include <cuda_runtime.h>

#define NN 100000
#define EE 1600000
#define NBLK1 391             // ceil(NN/256)
#define N0_BLOCKS 6250        // NN/16
#define HIST_BLOCKS 6250      // EE/256
#define FUSED_BLOCKS 112500   // 9 * 12500: 8 ae-blocks (16 edges each) : 1 other

typedef unsigned long long u64;

// ---------------- scratch (device globals; no allocation allowed) ----------
__device__ __align__(16) float g_ae[EE * 8];     // EDGE-ordered logits: h0-3 L1, h4-7 L2
__device__ __align__(16) float g_xp[NN * 64];    // projected node feats (25.6MB)
__device__ __align__(16) float g_acc[NN * 64];   // normalized aggregation (25.6MB)
__device__ __align__(16) int2  g_el2[EE];        // CSR: (src, edge_id) per slot (12.8MB)
__device__ float g_asrc[NN * 4];
__device__ float g_adst[NN * 4];
__device__ int   g_cnt[NN];
__device__ int   g_off[NN];
__device__ int   g_cur[NN];      // fill cursor; after fill = segment end
__device__ int   g_total;        // bump allocator
__device__ float g_P[512];       // folded [64 j][8 h], PRE-SCALED by 1/3
__device__ float g_W1t[64 * 128];   // transposed weights [c][k]
__device__ float g_W2t[64 * 64];
__device__ float g_Wot[64 * 64];

// ---------------------------------------------------------------------------
__device__ __forceinline__ u64 ffma2(u64 a, u64 b, u64 c) {
    u64 d;
    asm("fma.rn.f32x2 %0, %1, %2, %3;" : "=l"(d) : "l"(a), "l"(b), "l"(c));
    return d;
}
__device__ __forceinline__ float hsum2(u64 p) {
    return __uint_as_float((unsigned)p) + __uint_as_float((unsigned)(p >> 32));
}

// edge_index dtype hedge (int64 vs int32): int64 little-endian has zero odd words.
__device__ __forceinline__ bool ei_is64(const int* __restrict__ ei) {
    return (ei[1] | ei[3] | ei[5] | ei[7]) == 0;
}
__device__ __forceinline__ int ei_load(const int* __restrict__ ei, long long pos, bool is64) {
    return is64 ? ei[pos * 2] : ei[pos];
}

// ---------------------------------------------------------------------------
// setup: blocks 0..390 zero g_cnt (+g_total); block 391 folds P (x 1/3);
// blocks 392..423 transpose the three weight matrices.
// ---------------------------------------------------------------------------
__global__ void __launch_bounds__(256) setup_kernel(const float* __restrict__ We1,
                                                    const float* __restrict__ We2,
                                                    const float* __restrict__ ate1,
                                                    const float* __restrict__ ate2,
                                                    const float* __restrict__ W1,
                                                    const float* __restrict__ W2,
                                                    const float* __restrict__ Wo) {
    int b = blockIdx.x, t = threadIdx.x;
    if (b < NBLK1) {
        int i = b * 256 + t;
        if (i < NN) g_cnt[i] = 0;
        if (b == 0 && t == 0) g_total = 0;
    } else if (b == NBLK1) {
        __shared__ float A2p[64 * 4];
        int j = t;
        if (j < 64) {
#pragma unroll
            for (int h = 0; h < 4; h++) {
                float s = 0.f;
#pragma unroll
                for (int c = 0; c < 16; c++) s += We2[j * 64 + h * 16 + c] * ate2[h * 16 + c];
                A2p[j * 4 + h] = s;
            }
        }
        __syncthreads();
        if (j < 64) {
#pragma unroll
            for (int h = 0; h < 4; h++) {
                float s = 0.f;
#pragma unroll
                for (int c = 0; c < 16; c++) s += We1[j * 64 + h * 16 + c] * ate1[h * 16 + c];
                g_P[j * 8 + h] = s * (1.f / 3.f);           // fold mean's 1/3
            }
#pragma unroll
            for (int h = 0; h < 4; h++) {
                float s = 0.f;
                for (int k = 0; k < 64; k++) s += We1[j * 64 + k] * A2p[k * 4 + h];
                g_P[j * 8 + 4 + h] = s * (1.f / 3.f);
            }
        }
    } else {
        int i = (b - NBLK1 - 1) * 256 + t;   // 0..8191
        int k = i >> 6, c = i & 63;
        g_W1t[c * 128 + k] = W1[i];
        if (i < 4096) {
            g_W2t[c * 64 + k] = W2[i];
            g_Wot[c * 64 + k] = Wo[i];
        }
    }
}

// ---------------------------------------------------------------------------
// FUSED kernel, 3 interleaved block ranges (8 ae : 1 other):
//  ae   : smem-free edge-logit stream. Thread (e, j4) sums 3 quads, multiplies
//         a register-resident P slice, butterfly-reduces over the 16-lane
//         edge group, lane 0 writes 32B. 16 edges / block.
//  node0: layer-1 node GEMM (IN=128), f32x2, K staged in 2 halves.
//  hist : in-degree histogram (independent; overlaps ae's DRAM stream).
// ---------------------------------------------------------------------------
__global__ void __launch_bounds__(256) fused_kernel(const float* __restrict__ edge_attr,
                                                    const float* __restrict__ xin,
                                                    const float* __restrict__ attS,
                                                    const float* __restrict__ attD,
                                                    const int* __restrict__ ei) {
    __shared__ __align__(16) char sbuf[26368];
    int t = threadIdx.x;
    int bid = blockIdx.x;
    int r = bid % 9;

    if (r != 0) {
        // ---------------- ae body ------------------------------------------
        long long ae_idx = (long long)(bid / 9) * 8 + (r - 1);
        long long e = ae_idx * 16 + (t >> 4);
        int j4 = t & 15;
        const float4* __restrict__ P4 = (const float4*)g_P;
        int j0 = j4 * 4;
        float4 r0l = P4[(j0 + 0) * 2], r0h = P4[(j0 + 0) * 2 + 1];
        float4 r1l = P4[(j0 + 1) * 2], r1h = P4[(j0 + 1) * 2 + 1];
        float4 r2l = P4[(j0 + 2) * 2], r2h = P4[(j0 + 2) * 2 + 1];
        float4 r3l = P4[(j0 + 3) * 2], r3h = P4[(j0 + 3) * 2 + 1];

        const float4* __restrict__ ea4 = (const float4*)edge_attr;
        long long base = e * 48;
        float4 a = ea4[base + j4];
        float4 b = ea4[base + 16 + j4];
        float4 c = ea4[base + 32 + j4];
        float m0 = a.x + b.x + c.x;
        float m1 = a.y + b.y + c.y;
        float m2 = a.z + b.z + c.z;
        float m3 = a.w + b.w + c.w;

        float4 lo = make_float4(
            m0 * r0l.x + m1 * r1l.x + m2 * r2l.x + m3 * r3l.x,
            m0 * r0l.y + m1 * r1l.y + m2 * r2l.y + m3 * r3l.y,
            m0 * r0l.z + m1 * r1l.z + m2 * r2l.z + m3 * r3l.z,
            m0 * r0l.w + m1 * r1l.w + m2 * r2l.w + m3 * r3l.w);
        float4 hi = make_float4(
            m0 * r0h.x + m1 * r1h.x + m2 * r2h.x + m3 * r3h.x,
            m0 * r0h.y + m1 * r1h.y + m2 * r2h.y + m3 * r3h.y,
            m0 * r0h.z + m1 * r1h.z + m2 * r2h.z + m3 * r3h.z,
            m0 * r0h.w + m1 * r1h.w + m2 * r2h.w + m3 * r3h.w);

#pragma unroll
        for (int o = 1; o < 16; o <<= 1) {
            lo.x += __shfl_xor_sync(0xffffffffu, lo.x, o);
            lo.y += __shfl_xor_sync(0xffffffffu, lo.y, o);
            lo.z += __shfl_xor_sync(0xffffffffu, lo.z, o);
            lo.w += __shfl_xor_sync(0xffffffffu, lo.w, o);
            hi.x += __shfl_xor_sync(0xffffffffu, hi.x, o);
            hi.y += __shfl_xor_sync(0xffffffffu, hi.y, o);
            hi.z += __shfl_xor_sync(0xffffffffu, hi.z, o);
            hi.w += __shfl_xor_sync(0xffffffffu, hi.w, o);
        }
        if ((t & 15) == 0) {
            ((float4*)g_ae)[e * 2] = lo;
            ((float4*)g_ae)[e * 2 + 1] = hi;
        }
    } else {
        int o = bid / 9;
        if (o >= N0_BLOCKS) {
            // ---------------- hist body ------------------------------------
            int e = (o - N0_BLOCKS) * 256 + t;
            bool is64 = ei_is64(ei);
            int d = ei_load(ei, (long long)EE + e, is64);
            atomicAdd(&g_cnt[d], 1);
            return;
        }
        // ---------------- layer-1 node GEMM (IN=128) -----------------------
        const int INp = 132;
        float* Wts = (float*)sbuf;                     // 64 x 68 (one K half)
        float* xs = (float*)(sbuf + 17408);            // 16 x 132
        float* aSs = (float*)(sbuf + 25856);
        float* aDs = (float*)(sbuf + 26112);
        int nb0 = o * 16;

        for (int i = t; i < 16 * 128; i += 256)
            xs[(i >> 7) * INp + (i & 127)] = xin[(size_t)nb0 * 128 + i];
        if (t < 64) { aSs[t] = attS[t]; aDs[t] = attD[t]; }

        int c = t & 63, q = t >> 6;
        u64 p0 = 0ull, p1 = 0ull, p2 = 0ull, p3 = 0ull;
#pragma unroll
        for (int half = 0; half < 2; half++) {
            __syncthreads();
            for (int i = t; i < 4096; i += 256) {
                int cc = i >> 6, kk = i & 63;
                Wts[cc * 68 + kk] = g_W1t[cc * 128 + half * 64 + kk];
            }
            __syncthreads();
            const float* wr = &Wts[c * 68];
            const float* x0 = &xs[(q * 4 + 0) * INp + half * 64];
            const float* x1 = &xs[(q * 4 + 1) * INp + half * 64];
            const float* x2 = &xs[(q * 4 + 2) * INp + half * 64];
            const float* x3 = &xs[(q * 4 + 3) * INp + half * 64];
#pragma unroll
            for (int k = 0; k < 64; k += 4) {
                ulonglong2 w  = *(const ulonglong2*)&wr[k];
                ulonglong2 u0 = *(const ulonglong2*)&x0[k];
                ulonglong2 u1 = *(const ulonglong2*)&x1[k];
                ulonglong2 u2 = *(const ulonglong2*)&x2[k];
                ulonglong2 u3 = *(const ulonglong2*)&x3[k];
                p0 = ffma2(w.x, u0.x, p0); p0 = ffma2(w.y, u0.y, p0);
                p1 = ffma2(w.x, u1.x, p1); p1 = ffma2(w.y, u1.y, p1);
                p2 = ffma2(w.x, u2.x, p2); p2 = ffma2(w.y, u2.y, p2);
                p3 = ffma2(w.x, u3.x, p3); p3 = ffma2(w.y, u3.y, p3);
            }
        }
        float av[4] = {hsum2(p0), hsum2(p1), hsum2(p2), hsum2(p3)};
        float aS = aSs[c], aD = aDs[c];
        int lane = t & 31, head = c >> 4;
        int nb = nb0 + q * 4;
#pragma unroll
        for (int j = 0; j < 4; j++) {
            g_xp[(size_t)(nb + j) * 64 + c] = av[j];
            float r1 = av[j] * aS;
            float r2 = av[j] * aD;
#pragma unroll
            for (int oo = 8; oo; oo >>= 1) {
                r1 += __shfl_xor_sync(0xffffffffu, r1, oo);
                r2 += __shfl_xor_sync(0xffffffffu, r2, oo);
            }
            if ((lane & 15) == 0) {
                g_asrc[(nb + j) * 4 + head] = r1;
                g_adst[(nb + j) * 4 + head] = r2;
            }
        }
    }
}

// ---------------------------------------------------------------------------
// alloc: warp-aggregated bump allocation of CSR segments (order arbitrary,
// consistent within a launch; per-node sums unaffected).
// ---------------------------------------------------------------------------
__global__ void __launch_bounds__(256) alloc_kernel() {
    int i = blockIdx.x * 256 + threadIdx.x;
    int lane = threadIdx.x & 31;
    int c = (i < NN) ? g_cnt[i] : 0;
    int incl = c;
#pragma unroll
    for (int o = 1; o < 32; o <<= 1) {
        int v = __shfl_up_sync(0xffffffffu, incl, o);
        if (lane >= o) incl += v;
    }
    int wsum = __shfl_sync(0xffffffffu, incl, 31);
    int base = 0;
    if (lane == 31) base = atomicAdd(&g_total, wsum);
    base = __shfl_sync(0xffffffffu, base, 31);
    if (i < NN) {
        int off = base + incl - c;
        g_off[i] = off;
        g_cur[i] = off;
    }
}

__global__ void fill_kernel(const int* __restrict__ ei) {
    int e = blockIdx.x * 256 + threadIdx.x;
    bool is64 = ei_is64(ei);
    int s = ei_load(ei, e, is64);
    int d = ei_load(ei, (long long)EE + e, is64);
    int pos = atomicAdd(&g_cur[d], 1);
    g_el2[pos] = make_int2(s, e);
}

// ---------------------------------------------------------------------------
// Gather aggregation (per layer). One warp per node; lane owns channels 2l,2l+1;
// every lane computes the softmax weight for ITS head -> no shuffles/atomics.
// ---------------------------------------------------------------------------
template <int LAYER>
__global__ void __launch_bounds__(256) gather_kernel() {
    int lane = threadIdx.x & 31;
    int n = blockIdx.x * 8 + (threadIdx.x >> 5);
    int h = lane >> 3;
    const float2* __restrict__ xp2 = (const float2*)g_xp;
    float aD = g_adst[n * 4 + h];
    int p = g_off[n], pend = g_cur[n];
    float2 acc = make_float2(0.f, 0.f);
    float den = 0.f;
#pragma unroll 4
    for (; p < pend; p++) {
        int2 se = g_el2[p];
        float a = g_asrc[se.x * 4 + h] + aD + g_ae[(size_t)se.y * 8 + LAYER * 4 + h];
        a = a > 0.f ? a : 0.2f * a;
        float w = __expf(a);
        float2 v = xp2[se.x * 32 + lane];
        acc.x += w * v.x;
        acc.y += w * v.y;
        den += w;
    }
    float inv = 1.f / fmaxf(den, 1e-16f);
    ((float2*)g_acc)[n * 32 + lane] = make_float2(acc.x * inv, acc.y * inv);
}

// ---------------------------------------------------------------------------
// Node GEMM for layer-2 / output (IN=64), register-blocked f32x2.
// WSEL selects device weight array inside device code (1=W2t, 2=Wot).
// ---------------------------------------------------------------------------
template <int MODE, int WSEL>
__global__ void __launch_bounds__(256) node_kernel(const float* __restrict__ attS,
                                                   const float* __restrict__ attD,
                                                   const float* __restrict__ bias,
                                                   float* __restrict__ outp) {
    const float* __restrict__ Wt = (WSEL == 1) ? g_W2t : g_Wot;
    const int IN = 64, INp = 68;
    __shared__ float Wts[64 * INp];
    __shared__ float xs[16 * INp];
    __shared__ float aSs[64], aDs[64];
    int t = threadIdx.x;
    for (int i = t; i < 64 * IN; i += 256) Wts[(i >> 6) * INp + (i & 63)] = Wt[i];
    if (MODE == 1 && t < 64) { aSs[t] = attS[t]; aDs[t] = attD[t]; }
    int nb0 = blockIdx.x * 16;
    for (int i = t; i < 16 * 64; i += 256)
        xs[(i >> 6) * INp + (i & 63)] = fmaxf(g_acc[(size_t)nb0 * 64 + i], 0.f);
    __syncthreads();

    int c = t & 63, q = t >> 6;
    const float* wr = &Wts[c * INp];
    const float* x0 = &xs[(q * 4 + 0) * INp];
    const float* x1 = &xs[(q * 4 + 1) * INp];
    const float* x2 = &xs[(q * 4 + 2) * INp];
    const float* x3 = &xs[(q * 4 + 3) * INp];
    u64 p0 = 0ull, p1 = 0ull, p2 = 0ull, p3 = 0ull;
#pragma unroll
    for (int k = 0; k < IN; k += 4) {
        ulonglong2 w  = *(const ulonglong2*)&wr[k];
        ulonglong2 u0 = *(const ulonglong2*)&x0[k];
        ulonglong2 u1 = *(const ulonglong2*)&x1[k];
        ulonglong2 u2 = *(const ulonglong2*)&x2[k];
        ulonglong2 u3 = *(const ulonglong2*)&x3[k];
        p0 = ffma2(w.x, u0.x, p0); p0 = ffma2(w.y, u0.y, p0);
        p1 = ffma2(w.x, u1.x, p1); p1 = ffma2(w.y, u1.y, p1);
        p2 = ffma2(w.x, u2.x, p2); p2 = ffma2(w.y, u2.y, p2);
        p3 = ffma2(w.x, u3.x, p3); p3 = ffma2(w.y, u3.y, p3);
    }
    float a0 = hsum2(p0), a1 = hsum2(p1), a2 = hsum2(p2), a3 = hsum2(p3);
    int nb = nb0 + q * 4;
    if (MODE == 2) {
        float b = bias[c];
        outp[(size_t)(nb + 0) * 64 + c] = a0 + b;
        outp[(size_t)(nb + 1) * 64 + c] = a1 + b;
        outp[(size_t)(nb + 2) * 64 + c] = a2 + b;
        outp[(size_t)(nb + 3) * 64 + c] = a3 + b;
    } else {
        float aS = aSs[c], aD = aDs[c];
        int lane = t & 31, head = c >> 4;
        float av[4] = {a0, a1, a2, a3};
#pragma unroll
        for (int j = 0; j < 4; j++) {
            g_xp[(size_t)(nb + j) * 64 + c] = av[j];
            float r1 = av[j] * aS;
            float r2 = av[j] * aD;
#pragma unroll
            for (int o = 8; o; o >>= 1) {
                r1 += __shfl_xor_sync(0xffffffffu, r1, o);
                r2 += __shfl_xor_sync(0xffffffffu, r2, o);
            }
            if ((lane & 15) == 0) {
                g_asrc[(nb + j) * 4 + head] = r1;
                g_adst[(nb + j) * 4 + head] = r2;
            }
        }
    }
}

// ---------------------------------------------------------------------------
extern "C" void kernel_launch(void* const* d_in, const int* in_sizes, int n_in,
                              void* d_out, int out_size) {
    const float* x = (const float*)d_in[0];
    const int* ei = (const int*)d_in[1];
    const float* edge_attr = (const float*)d_in[2];
    const float* W1 = (const float*)d_in[3];
    const float* We1 = (const float*)d_in[4];
    const float* as1 = (const float*)d_in[5];
    const float* ad1 = (const float*)d_in[6];
    const float* ae1 = (const float*)d_in[7];
    const float* W2 = (const float*)d_in[8];
    const float* We2 = (const float*)d_in[9];
    const float* as2 = (const float*)d_in[10];
    const float* ad2 = (const float*)d_in[11];
    const float* ae2 = (const float*)d_in[12];
    const float* Wout = (const float*)d_in[13];
    const float* bout = (const float*)d_in[14];
    float* out = (float*)d_out;

    // 1: zero cnt/total + P fold (x1/3) + weight transpose
    setup_kernel<<<NBLK1 + 1 + 32, 256>>>(We1, We2, ae1, ae2, W1, W2, Wout);
    // 2: big fused kernel: ae stream + layer-1 node GEMM + degree histogram
    fused_kernel<<<FUSED_BLOCKS, 256>>>(edge_attr, x, as1, ad1, ei);
    // 3-4: CSR segments (bump alloc) + fill
    alloc_kernel<<<NBLK1, 256>>>();
    fill_kernel<<<EE / 256, 256>>>(ei);
    // 5-8: aggregation + remaining layers
    gather_kernel<0><<<NN / 8, 256>>>();
    node_kernel<1, 1><<<NN / 16, 256>>>(as2, ad2, nullptr, nullptr);
    gather_kernel<1><<<NN / 8, 256>>>();
    node_kernel<2, 2><<<NN / 16, 256>>>(nullptr, nullptr, bout, out);
}

// round 12
// speedup vs baseline: 2.0064x; 2.0064x over previous
#include <cuda_runtime.h>

#define NN 100000
#define EE 1600000
#define NBLK1 391             // ceil(NN/256)
#define AE_BLOCKS (EE / 32)   // 50000
#define N0_BLOCKS (NN / 16)   // 6250

typedef unsigned long long u64;

// ---------------- scratch (device globals; no allocation allowed) ----------
__device__ __align__(16) float g_ae[EE * 8];     // EDGE-ordered logits: h0-3 L1, h4-7 L2
__device__ __align__(16) float g_xp[NN * 64];    // layer-1 projected feats
__device__ __align__(16) float g_xp2[NN * 64];   // layer-2 projected feats
__device__ __align__(16) int2  g_el2[EE];        // CSR: (src, edge_id) per slot
__device__ float g_asrc[NN * 4],  g_adst[NN * 4];    // layer-1 att dots
__device__ float g_asrc2[NN * 4], g_adst2[NN * 4];   // layer-2 att dots
__device__ int   g_cnt[NN];
__device__ int   g_off[NN];
__device__ int   g_cur[NN];      // fill cursor; after fill = segment end
__device__ int   g_total;        // bump allocator
__device__ float g_P[512];       // folded [64 j][8 h]
__device__ float g_W1t[64 * 128];   // transposed weights [c][k]
__device__ float g_W2t[64 * 64];
__device__ float g_Wot[64 * 64];

// ---------------------------------------------------------------------------
__device__ __forceinline__ u64 ffma2(u64 a, u64 b, u64 c) {
    u64 d;
    asm("fma.rn.f32x2 %0, %1, %2, %3;" : "=l"(d) : "l"(a), "l"(b), "l"(c));
    return d;
}
__device__ __forceinline__ float hsum2(u64 p) {
    return __uint_as_float((unsigned)p) + __uint_as_float((unsigned)(p >> 32));
}

// edge_index dtype hedge (int64 vs int32): int64 little-endian has zero odd words.
__device__ __forceinline__ bool ei_is64(const int* __restrict__ ei) {
    return (ei[1] | ei[3] | ei[5] | ei[7]) == 0;
}
__device__ __forceinline__ int ei_load(const int* __restrict__ ei, long long pos, bool is64) {
    return is64 ? ei[pos * 2] : ei[pos];
}

// ---------------------------------------------------------------------------
// setup: blocks 0..390 zero g_cnt (+g_total); block 391 folds P; blocks
// 392..423 transpose the three weight matrices.
// ---------------------------------------------------------------------------
__global__ void __launch_bounds__(256) setup_kernel(const float* __restrict__ We1,
                                                    const float* __restrict__ We2,
                                                    const float* __restrict__ ate1,
                                                    const float* __restrict__ ate2,
                                                    const float* __restrict__ W1,
                                                    const float* __restrict__ W2,
                                                    const float* __restrict__ Wo) {
    int b = blockIdx.x, t = threadIdx.x;
    if (b < NBLK1) {
        int i = b * 256 + t;
        if (i < NN) g_cnt[i] = 0;
        if (b == 0 && t == 0) g_total = 0;
    } else if (b == NBLK1) {
        __shared__ float A2p[64 * 4];
        int j = t;
        if (j < 64) {
#pragma unroll
            for (int h = 0; h < 4; h++) {
                float s = 0.f;
#pragma unroll
                for (int c = 0; c < 16; c++) s += We2[j * 64 + h * 16 + c] * ate2[h * 16 + c];
                A2p[j * 4 + h] = s;
            }
        }
        __syncthreads();
        if (j < 64) {
#pragma unroll
            for (int h = 0; h < 4; h++) {
                float s = 0.f;
#pragma unroll
                for (int c = 0; c < 16; c++) s += We1[j * 64 + h * 16 + c] * ate1[h * 16 + c];
                g_P[j * 8 + h] = s;
            }
#pragma unroll
            for (int h = 0; h < 4; h++) {
                float s = 0.f;
                for (int k = 0; k < 64; k++) s += We1[j * 64 + k] * A2p[k * 4 + h];
                g_P[j * 8 + 4 + h] = s;
            }
        }
    } else {
        int i = (b - NBLK1 - 1) * 256 + t;   // 0..8191
        int k = i >> 6, c = i & 63;
        g_W1t[c * 128 + k] = W1[i];
        if (i < 4096) {
            g_W2t[c * 64 + k] = W2[i];
            g_Wot[c * 64 + k] = Wo[i];
        }
    }
}

// ---------------------------------------------------------------------------
// CSR build helpers: histogram, warp-aggregated bump alloc, fill
// (alloc order arbitrary-but-consistent; per-node sums unaffected)
// ---------------------------------------------------------------------------
__global__ void hist_kernel(const int* __restrict__ ei) {
    int e = blockIdx.x * 256 + threadIdx.x;
    bool is64 = ei_is64(ei);
    int d = ei_load(ei, (long long)EE + e, is64);
    atomicAdd(&g_cnt[d], 1);
}
__global__ void __launch_bounds__(256) alloc_kernel() {
    int i = blockIdx.x * 256 + threadIdx.x;
    int lane = threadIdx.x & 31;
    int c = (i < NN) ? g_cnt[i] : 0;
    int incl = c;
#pragma unroll
    for (int o = 1; o < 32; o <<= 1) {
        int v = __shfl_up_sync(0xffffffffu, incl, o);
        if (lane >= o) incl += v;
    }
    int wsum = __shfl_sync(0xffffffffu, incl, 31);
    int base = 0;
    if (lane == 31) base = atomicAdd(&g_total, wsum);
    base = __shfl_sync(0xffffffffu, base, 31);
    if (i < NN) {
        int off = base + incl - c;
        g_off[i] = off;
        g_cur[i] = off;
    }
}
__global__ void fill_kernel(const int* __restrict__ ei) {
    int e = blockIdx.x * 256 + threadIdx.x;
    bool is64 = ei_is64(ei);
    int s = ei_load(ei, e, is64);
    int d = ei_load(ei, (long long)EE + e, is64);
    int pos = atomicAdd(&g_cur[d], 1);
    g_el2[pos] = make_int2(s, e);
}

// ---------------------------------------------------------------------------
// FUSED kernel (R9-proven): blocks [0, AE_BLOCKS) = ae body; rest = layer-1
// node GEMM. Shared buffer is a union of both layouts.
// ---------------------------------------------------------------------------
__global__ void __launch_bounds__(256) fused_ae_node0_kernel(
        const float* __restrict__ edge_attr,
        const float* __restrict__ xin,
        const float* __restrict__ attS,
        const float* __restrict__ attD) {
    __shared__ __align__(16) char sbuf[26368];
    int t = threadIdx.x;

    if (blockIdx.x < AE_BLOCKS) {
        // ---------------- ae body: g_ae[e][0:8] = mean(edge_attr[e]) @ P ----
        float* sEas = (float*)sbuf;            // 32 x 68
        float* sPt = (float*)(sbuf + 8704);    // 8 x 68 (transposed P)
        const float4* __restrict__ ea4 = (const float4*)edge_attr;
        long long e0 = (long long)blockIdx.x * 32;

#pragma unroll
        for (int i = 0; i < 2; i++) {
            int idx = t + i * 256;
            sPt[(idx & 7) * 68 + (idx >> 3)] = g_P[idx];
        }
#pragma unroll
        for (int i = 0; i < 2; i++) {
            int idx = t + i * 256;           // 0..511
            int e = idx >> 4, j4 = idx & 15;
            long long base = (e0 + e) * 48;
            float4 a = ea4[base + j4];
            float4 b = ea4[base + 16 + j4];
            float4 c = ea4[base + 32 + j4];
            float4 m = make_float4((a.x + b.x + c.x) * (1.f / 3.f),
                                   (a.y + b.y + c.y) * (1.f / 3.f),
                                   (a.z + b.z + c.z) * (1.f / 3.f),
                                   (a.w + b.w + c.w) * (1.f / 3.f));
            *(float4*)&sEas[e * 68 + j4 * 4] = m;
        }
        __syncthreads();

        int e = t >> 3, h = t & 7;
        const float* er = &sEas[e * 68];
        const float* pr = &sPt[h * 68];
        float acc = 0.f;
#pragma unroll
        for (int j4 = 0; j4 < 16; j4++) {
            float4 u = *(const float4*)&er[j4 * 4];
            float4 p = *(const float4*)&pr[j4 * 4];
            acc += u.x * p.x + u.y * p.y + u.z * p.z + u.w * p.w;
        }
        g_ae[(e0 + e) * 8 + h] = acc;        // fully coalesced (edge order)
    } else {
        // ---------------- layer-1 node GEMM (IN=128), K staged in 2 halves --
        const int INp = 132;
        float* Wts = (float*)sbuf;                     // 64 x 68 (one K half)
        float* xs = (float*)(sbuf + 17408);            // 16 x 132
        float* aSs = (float*)(sbuf + 25856);
        float* aDs = (float*)(sbuf + 26112);
        int nb0 = (blockIdx.x - AE_BLOCKS) * 16;

        for (int i = t; i < 16 * 128; i += 256)
            xs[(i >> 7) * INp + (i & 127)] = xin[(size_t)nb0 * 128 + i];
        if (t < 64) { aSs[t] = attS[t]; aDs[t] = attD[t]; }

        int c = t & 63, q = t >> 6;
        u64 p0 = 0ull, p1 = 0ull, p2 = 0ull, p3 = 0ull;
#pragma unroll
        for (int half = 0; half < 2; half++) {
            __syncthreads();
            for (int i = t; i < 4096; i += 256) {
                int cc = i >> 6, kk = i & 63;
                Wts[cc * 68 + kk] = g_W1t[cc * 128 + half * 64 + kk];
            }
            __syncthreads();
            const float* wr = &Wts[c * 68];
            const float* x0 = &xs[(q * 4 + 0) * INp + half * 64];
            const float* x1 = &xs[(q * 4 + 1) * INp + half * 64];
            const float* x2 = &xs[(q * 4 + 2) * INp + half * 64];
            const float* x3 = &xs[(q * 4 + 3) * INp + half * 64];
#pragma unroll
            for (int k = 0; k < 64; k += 4) {
                ulonglong2 w  = *(const ulonglong2*)&wr[k];
                ulonglong2 u0 = *(const ulonglong2*)&x0[k];
                ulonglong2 u1 = *(const ulonglong2*)&x1[k];
                ulonglong2 u2 = *(const ulonglong2*)&x2[k];
                ulonglong2 u3 = *(const ulonglong2*)&x3[k];
                p0 = ffma2(w.x, u0.x, p0); p0 = ffma2(w.y, u0.y, p0);
                p1 = ffma2(w.x, u1.x, p1); p1 = ffma2(w.y, u1.y, p1);
                p2 = ffma2(w.x, u2.x, p2); p2 = ffma2(w.y, u2.y, p2);
                p3 = ffma2(w.x, u3.x, p3); p3 = ffma2(w.y, u3.y, p3);
            }
        }
        float av[4] = {hsum2(p0), hsum2(p1), hsum2(p2), hsum2(p3)};
        float aS = aSs[c], aD = aDs[c];
        int lane = t & 31, head = c >> 4;
        int nb = nb0 + q * 4;
#pragma unroll
        for (int j = 0; j < 4; j++) {
            g_xp[(size_t)(nb + j) * 64 + c] = av[j];
            float r1 = av[j] * aS;
            float r2 = av[j] * aD;
#pragma unroll
            for (int o = 8; o; o >>= 1) {
                r1 += __shfl_xor_sync(0xffffffffu, r1, o);
                r2 += __shfl_xor_sync(0xffffffffu, r2, o);
            }
            if ((lane & 15) == 0) {
                g_asrc[(nb + j) * 4 + head] = r1;
                g_adst[(nb + j) * 4 + head] = r2;
            }
        }
    }
}

// ---------------------------------------------------------------------------
// FUSED gather + node GEMM. Block = 16 nodes.
// Gather phase: 16 groups of 16 lanes; group g owns node nb0+g, lane owns a
// float4 of channels (4l..4l+3, all in head l>>2 -> per-lane softmax weight,
// no shuffles/atomics). Normalized relu'd result goes straight to smem xs.
// GEMM phase (after one __syncthreads): proven register-blocked f32x2 GEMM.
// LAYER 1: xp/att from layer-1 bufs, g_ae cols 0-3, W2t -> g_xp2 + att2 dots.
// LAYER 2: xp/att from layer-2 bufs, g_ae cols 4-7, Wot -> out + bias.
// ---------------------------------------------------------------------------
template <int LAYER>
__global__ void __launch_bounds__(256) gather_node_kernel(const float* __restrict__ attS,
                                                          const float* __restrict__ attD,
                                                          const float* __restrict__ bias,
                                                          float* __restrict__ outp) {
    const int INp = 68;
    __shared__ float Wts[64 * INp];
    __shared__ float xs[16 * INp];
    __shared__ float aSs[64], aDs[64];
    int t = threadIdx.x;
    const float* __restrict__ Wt = (LAYER == 1) ? g_W2t : g_Wot;
    for (int i = t; i < 64 * 64; i += 256) Wts[(i >> 6) * INp + (i & 63)] = Wt[i];
    if (LAYER == 1 && t < 64) { aSs[t] = attS[t]; aDs[t] = attD[t]; }

    // ---- gather phase ----
    int grp = t >> 4, gl = t & 15;
    int nb0 = blockIdx.x * 16;
    int n = nb0 + grp;
    int h = gl >> 2;
    const float* __restrict__ aSrc = (LAYER == 1) ? g_asrc : g_asrc2;
    const float* __restrict__ aDst = (LAYER == 1) ? g_adst : g_adst2;
    const float4* __restrict__ xp4 =
        (const float4*)((LAYER == 1) ? g_xp : g_xp2);
    float aD = aDst[n * 4 + h];
    int p = g_off[n], pend = g_cur[n];
    float4 acc = make_float4(0.f, 0.f, 0.f, 0.f);
    float den = 0.f;
#pragma unroll 4
    for (; p < pend; p++) {
        int2 se = g_el2[p];
        float a = aSrc[se.x * 4 + h] + aD + g_ae[(size_t)se.y * 8 + (LAYER - 1) * 4 + h];
        a = a > 0.f ? a : 0.2f * a;
        float w = __expf(a);
        float4 v = xp4[se.x * 16 + gl];
        acc.x += w * v.x;
        acc.y += w * v.y;
        acc.z += w * v.z;
        acc.w += w * v.w;
        den += w;
    }
    float inv = 1.f / fmaxf(den, 1e-16f);
    *(float4*)&xs[grp * INp + gl * 4] =
        make_float4(fmaxf(acc.x * inv, 0.f), fmaxf(acc.y * inv, 0.f),
                    fmaxf(acc.z * inv, 0.f), fmaxf(acc.w * inv, 0.f));
    __syncthreads();

    // ---- GEMM phase ----
    int c = t & 63, q = t >> 6;
    const float* wr = &Wts[c * INp];
    const float* x0 = &xs[(q * 4 + 0) * INp];
    const float* x1 = &xs[(q * 4 + 1) * INp];
    const float* x2 = &xs[(q * 4 + 2) * INp];
    const float* x3 = &xs[(q * 4 + 3) * INp];
    u64 p0 = 0ull, p1 = 0ull, p2 = 0ull, p3 = 0ull;
#pragma unroll
    for (int k = 0; k < 64; k += 4) {
        ulonglong2 w  = *(const ulonglong2*)&wr[k];
        ulonglong2 u0 = *(const ulonglong2*)&x0[k];
        ulonglong2 u1 = *(const ulonglong2*)&x1[k];
        ulonglong2 u2 = *(const ulonglong2*)&x2[k];
        ulonglong2 u3 = *(const ulonglong2*)&x3[k];
        p0 = ffma2(w.x, u0.x, p0); p0 = ffma2(w.y, u0.y, p0);
        p1 = ffma2(w.x, u1.x, p1); p1 = ffma2(w.y, u1.y, p1);
        p2 = ffma2(w.x, u2.x, p2); p2 = ffma2(w.y, u2.y, p2);
        p3 = ffma2(w.x, u3.x, p3); p3 = ffma2(w.y, u3.y, p3);
    }
    float a0 = hsum2(p0), a1 = hsum2(p1), a2 = hsum2(p2), a3 = hsum2(p3);
    int nb = nb0 + q * 4;
    if (LAYER == 2) {
        float b = bias[c];
        outp[(size_t)(nb + 0) * 64 + c] = a0 + b;
        outp[(size_t)(nb + 1) * 64 + c] = a1 + b;
        outp[(size_t)(nb + 2) * 64 + c] = a2 + b;
        outp[(size_t)(nb + 3) * 64 + c] = a3 + b;
    } else {
        float aS = aSs[c], aDv = aDs[c];
        int lane = t & 31, head = c >> 4;
        float av[4] = {a0, a1, a2, a3};
#pragma unroll
        for (int j = 0; j < 4; j++) {
            g_xp2[(size_t)(nb + j) * 64 + c] = av[j];
            float r1 = av[j] * aS;
            float r2 = av[j] * aDv;
#pragma unroll
            for (int o = 8; o; o >>= 1) {
                r1 += __shfl_xor_sync(0xffffffffu, r1, o);
                r2 += __shfl_xor_sync(0xffffffffu, r2, o);
            }
            if ((lane & 15) == 0) {
                g_asrc2[(nb + j) * 4 + head] = r1;
                g_adst2[(nb + j) * 4 + head] = r2;
            }
        }
    }
}

// ---------------------------------------------------------------------------
extern "C" void kernel_launch(void* const* d_in, const int* in_sizes, int n_in,
                              void* d_out, int out_size) {
    const float* x = (const float*)d_in[0];
    const int* ei = (const int*)d_in[1];
    const float* edge_attr = (const float*)d_in[2];
    const float* W1 = (const float*)d_in[3];
    const float* We1 = (const float*)d_in[4];
    const float* as1 = (const float*)d_in[5];
    const float* ad1 = (const float*)d_in[6];
    const float* ae1 = (const float*)d_in[7];
    const float* W2 = (const float*)d_in[8];
    const float* We2 = (const float*)d_in[9];
    const float* as2 = (const float*)d_in[10];
    const float* ad2 = (const float*)d_in[11];
    const float* ae2 = (const float*)d_in[12];
    const float* Wout = (const float*)d_in[13];
    const float* bout = (const float*)d_in[14];
    float* out = (float*)d_out;

    // 1: zero cnt/total + P fold + weight transpose
    setup_kernel<<<NBLK1 + 1 + 32, 256>>>(We1, We2, ae1, ae2, W1, W2, Wout);
    // 2-4: CSR build (histogram -> bump alloc -> fill)
    hist_kernel<<<EE / 256, 256>>>(ei);
    alloc_kernel<<<NBLK1, 256>>>();
    fill_kernel<<<EE / 256, 256>>>(ei);
    // 5: big fused kernel (ae stream + layer-1 node GEMM)
    fused_ae_node0_kernel<<<AE_BLOCKS + N0_BLOCKS, 256>>>(edge_attr, x, as1, ad1);
    // 6: gather layer 1 + layer-2 node GEMM (writes xp2/att2)
    gather_node_kernel<1><<<NN / 16, 256>>>(as2, ad2, nullptr, nullptr);
    // 7: gather layer 2 + output GEMM
    gather_node_kernel<2><<<NN / 16, 256>>>(nullptr, nullptr, bout, out);
}

// round 13
// speedup vs baseline: 2.1889x; 1.0910x over previous
#include <cuda_runtime.h>

#define NN 100000
#define EE 1600000
#define NBLK1 391             // ceil(NN/256)
#define AE_BLOCKS (EE / 64)   // 25000 (64 edges per ae block)
#define N0_BLOCKS (NN / 16)   // 6250

typedef unsigned long long u64;

// ---------------- scratch (device globals; no allocation allowed) ----------
__device__ __align__(16) float g_ae1[EE * 4];    // layer-1 edge logits (25.6MB)
__device__ __align__(16) float g_ae2[EE * 4];    // layer-2 edge logits (25.6MB)
__device__ __align__(16) float g_xp[NN * 64];    // layer-1 projected feats
__device__ __align__(16) float g_xp2[NN * 64];   // layer-2 projected feats
__device__ __align__(16) int2  g_el2[EE];        // CSR: (src, edge_id) per slot
__device__ float g_asrc[NN * 4],  g_adst[NN * 4];    // layer-1 att dots
__device__ float g_asrc2[NN * 4], g_adst2[NN * 4];   // layer-2 att dots
__device__ int   g_cnt[NN];
__device__ int   g_off[NN];
__device__ int   g_cur[NN];      // fill cursor; after fill = segment end
__device__ int   g_total;        // bump allocator
__device__ float g_P[512];       // folded [64 j][8 h]
__device__ float g_W1t[64 * 128];   // transposed weights [c][k]
__device__ float g_W2t[64 * 64];
__device__ float g_Wot[64 * 64];

// ---------------------------------------------------------------------------
__device__ __forceinline__ u64 ffma2(u64 a, u64 b, u64 c) {
    u64 d;
    asm("fma.rn.f32x2 %0, %1, %2, %3;" : "=l"(d) : "l"(a), "l"(b), "l"(c));
    return d;
}
__device__ __forceinline__ float hsum2(u64 p) {
    return __uint_as_float((unsigned)p) + __uint_as_float((unsigned)(p >> 32));
}

// edge_index dtype hedge (int64 vs int32): int64 little-endian has zero odd words.
__device__ __forceinline__ bool ei_is64(const int* __restrict__ ei) {
    return (ei[1] | ei[3] | ei[5] | ei[7]) == 0;
}
__device__ __forceinline__ int ei_load(const int* __restrict__ ei, long long pos, bool is64) {
    return is64 ? ei[pos * 2] : ei[pos];
}

// ---------------------------------------------------------------------------
// setup: blocks 0..390 zero g_cnt (+g_total); block 391 folds P; blocks
// 392..423 transpose the three weight matrices.
// ---------------------------------------------------------------------------
__global__ void __launch_bounds__(256) setup_kernel(const float* __restrict__ We1,
                                                    const float* __restrict__ We2,
                                                    const float* __restrict__ ate1,
                                                    const float* __restrict__ ate2,
                                                    const float* __restrict__ W1,
                                                    const float* __restrict__ W2,
                                                    const float* __restrict__ Wo) {
    int b = blockIdx.x, t = threadIdx.x;
    if (b < NBLK1) {
        int i = b * 256 + t;
        if (i < NN) g_cnt[i] = 0;
        if (b == 0 && t == 0) g_total = 0;
    } else if (b == NBLK1) {
        __shared__ float A2p[64 * 4];
        int j = t;
        if (j < 64) {
#pragma unroll
            for (int h = 0; h < 4; h++) {
                float s = 0.f;
#pragma unroll
                for (int c = 0; c < 16; c++) s += We2[j * 64 + h * 16 + c] * ate2[h * 16 + c];
                A2p[j * 4 + h] = s;
            }
        }
        __syncthreads();
        if (j < 64) {
#pragma unroll
            for (int h = 0; h < 4; h++) {
                float s = 0.f;
#pragma unroll
                for (int c = 0; c < 16; c++) s += We1[j * 64 + h * 16 + c] * ate1[h * 16 + c];
                g_P[j * 8 + h] = s;
            }
#pragma unroll
            for (int h = 0; h < 4; h++) {
                float s = 0.f;
                for (int k = 0; k < 64; k++) s += We1[j * 64 + k] * A2p[k * 4 + h];
                g_P[j * 8 + 4 + h] = s;
            }
        }
    } else {
        int i = (b - NBLK1 - 1) * 256 + t;   // 0..8191
        int k = i >> 6, c = i & 63;
        g_W1t[c * 128 + k] = W1[i];
        if (i < 4096) {
            g_W2t[c * 64 + k] = W2[i];
            g_Wot[c * 64 + k] = Wo[i];
        }
    }
}

// ---------------------------------------------------------------------------
// CSR build helpers: histogram, warp-aggregated bump alloc, fill
// ---------------------------------------------------------------------------
__global__ void hist_kernel(const int* __restrict__ ei) {
    int e = blockIdx.x * 256 + threadIdx.x;
    bool is64 = ei_is64(ei);
    int d = ei_load(ei, (long long)EE + e, is64);
    atomicAdd(&g_cnt[d], 1);
}
__global__ void __launch_bounds__(256) alloc_kernel() {
    int i = blockIdx.x * 256 + threadIdx.x;
    int lane = threadIdx.x & 31;
    int c = (i < NN) ? g_cnt[i] : 0;
    int incl = c;
#pragma unroll
    for (int o = 1; o < 32; o <<= 1) {
        int v = __shfl_up_sync(0xffffffffu, incl, o);
        if (lane >= o) incl += v;
    }
    int wsum = __shfl_sync(0xffffffffu, incl, 31);
    int base = 0;
    if (lane == 31) base = atomicAdd(&g_total, wsum);
    base = __shfl_sync(0xffffffffu, base, 31);
    if (i < NN) {
        int off = base + incl - c;
        g_off[i] = off;
        g_cur[i] = off;
    }
}
__global__ void fill_kernel(const int* __restrict__ ei) {
    int e = blockIdx.x * 256 + threadIdx.x;
    bool is64 = ei_is64(ei);
    int s = ei_load(ei, e, is64);
    int d = ei_load(ei, (long long)EE + e, is64);
    int pos = atomicAdd(&g_cur[d], 1);
    g_el2[pos] = make_int2(s, e);
}

// ---------------------------------------------------------------------------
// FUSED kernel: blocks [0, AE_BLOCKS) = ae body (64 edges/block, 2-edge
// P-register reuse in the matvec); rest = layer-1 node GEMM (R9-proven).
// ---------------------------------------------------------------------------
__global__ void __launch_bounds__(256) fused_ae_node0_kernel(
        const float* __restrict__ edge_attr,
        const float* __restrict__ xin,
        const float* __restrict__ attS,
        const float* __restrict__ attD) {
    __shared__ __align__(16) char sbuf[26368];
    int t = threadIdx.x;

    if (blockIdx.x < AE_BLOCKS) {
        // ---- ae body: g_ae{1,2}[e][0:4] = mean(edge_attr[e]) @ P halves ----
        float* sEas = (float*)sbuf;            // 64 x 68 floats (17408B)
        float* sPt = (float*)(sbuf + 17408);   // 8 x 68 (transposed P, 2176B)
        const float4* __restrict__ ea4 = (const float4*)edge_attr;
        long long e0 = (long long)blockIdx.x * 64;

#pragma unroll
        for (int i = 0; i < 2; i++) {
            int idx = t + i * 256;
            sPt[(idx & 7) * 68 + (idx >> 3)] = g_P[idx];
        }
#pragma unroll
        for (int i = 0; i < 4; i++) {
            int idx = t + i * 256;           // 0..1023
            int e = idx >> 4, j4 = idx & 15;
            long long base = (e0 + e) * 48;
            float4 a = ea4[base + j4];
            float4 b = ea4[base + 16 + j4];
            float4 c = ea4[base + 32 + j4];
            float4 m = make_float4((a.x + b.x + c.x) * (1.f / 3.f),
                                   (a.y + b.y + c.y) * (1.f / 3.f),
                                   (a.z + b.z + c.z) * (1.f / 3.f),
                                   (a.w + b.w + c.w) * (1.f / 3.f));
            *(float4*)&sEas[e * 68 + j4 * 4] = m;
        }
        __syncthreads();

        // thread -> (edge pair g = t>>3, head h = t&7); pr reused for 2 edges
        int g = t >> 3, h = t & 7;
        const float* erA = &sEas[(g * 2 + 0) * 68];
        const float* erB = &sEas[(g * 2 + 1) * 68];
        const float* pr = &sPt[h * 68];
        float accA = 0.f, accB = 0.f;
#pragma unroll
        for (int j4 = 0; j4 < 16; j4++) {
            float4 p = *(const float4*)&pr[j4 * 4];
            float4 uA = *(const float4*)&erA[j4 * 4];
            float4 uB = *(const float4*)&erB[j4 * 4];
            accA += uA.x * p.x + uA.y * p.y + uA.z * p.z + uA.w * p.w;
            accB += uB.x * p.x + uB.y * p.y + uB.z * p.z + uB.w * p.w;
        }
        long long eA = e0 + g * 2, eB = eA + 1;
        if (h < 4) {
            g_ae1[eA * 4 + h] = accA;
            g_ae1[eB * 4 + h] = accB;
        } else {
            g_ae2[eA * 4 + (h - 4)] = accA;
            g_ae2[eB * 4 + (h - 4)] = accB;
        }
    } else {
        // ---------------- layer-1 node GEMM (IN=128), K staged in 2 halves --
        const int INp = 132;
        float* Wts = (float*)sbuf;                     // 64 x 68 (one K half)
        float* xs = (float*)(sbuf + 17408);            // 16 x 132
        float* aSs = (float*)(sbuf + 25856);
        float* aDs = (float*)(sbuf + 26112);
        int nb0 = (blockIdx.x - AE_BLOCKS) * 16;

        for (int i = t; i < 16 * 128; i += 256)
            xs[(i >> 7) * INp + (i & 127)] = xin[(size_t)nb0 * 128 + i];
        if (t < 64) { aSs[t] = attS[t]; aDs[t] = attD[t]; }

        int c = t & 63, q = t >> 6;
        u64 p0 = 0ull, p1 = 0ull, p2 = 0ull, p3 = 0ull;
#pragma unroll
        for (int half = 0; half < 2; half++) {
            __syncthreads();
            for (int i = t; i < 4096; i += 256) {
                int cc = i >> 6, kk = i & 63;
                Wts[cc * 68 + kk] = g_W1t[cc * 128 + half * 64 + kk];
            }
            __syncthreads();
            const float* wr = &Wts[c * 68];
            const float* x0 = &xs[(q * 4 + 0) * INp + half * 64];
            const float* x1 = &xs[(q * 4 + 1) * INp + half * 64];
            const float* x2 = &xs[(q * 4 + 2) * INp + half * 64];
            const float* x3 = &xs[(q * 4 + 3) * INp + half * 64];
#pragma unroll
            for (int k = 0; k < 64; k += 4) {
                ulonglong2 w  = *(const ulonglong2*)&wr[k];
                ulonglong2 u0 = *(const ulonglong2*)&x0[k];
                ulonglong2 u1 = *(const ulonglong2*)&x1[k];
                ulonglong2 u2 = *(const ulonglong2*)&x2[k];
                ulonglong2 u3 = *(const ulonglong2*)&x3[k];
                p0 = ffma2(w.x, u0.x, p0); p0 = ffma2(w.y, u0.y, p0);
                p1 = ffma2(w.x, u1.x, p1); p1 = ffma2(w.y, u1.y, p1);
                p2 = ffma2(w.x, u2.x, p2); p2 = ffma2(w.y, u2.y, p2);
                p3 = ffma2(w.x, u3.x, p3); p3 = ffma2(w.y, u3.y, p3);
            }
        }
        float av[4] = {hsum2(p0), hsum2(p1), hsum2(p2), hsum2(p3)};
        float aS = aSs[c], aD = aDs[c];
        int lane = t & 31, head = c >> 4;
        int nb = nb0 + q * 4;
#pragma unroll
        for (int j = 0; j < 4; j++) {
            g_xp[(size_t)(nb + j) * 64 + c] = av[j];
            float r1 = av[j] * aS;
            float r2 = av[j] * aD;
#pragma unroll
            for (int o = 8; o; o >>= 1) {
                r1 += __shfl_xor_sync(0xffffffffu, r1, o);
                r2 += __shfl_xor_sync(0xffffffffu, r2, o);
            }
            if ((lane & 15) == 0) {
                g_asrc[(nb + j) * 4 + head] = r1;
                g_adst[(nb + j) * 4 + head] = r2;
            }
        }
    }
}

// ---------------------------------------------------------------------------
// FUSED gather + node GEMM (R11-proven). Block = 16 nodes.
// Gather: 16 groups of 16 lanes; lane owns a float4 of channels (head l>>2).
// GEMM: register-blocked f32x2 on the smem tile.
// ---------------------------------------------------------------------------
template <int LAYER>
__global__ void __launch_bounds__(256) gather_node_kernel(const float* __restrict__ attS,
                                                          const float* __restrict__ attD,
                                                          const float* __restrict__ bias,
                                                          float* __restrict__ outp) {
    const int INp = 68;
    __shared__ float Wts[64 * INp];
    __shared__ float xs[16 * INp];
    __shared__ float aSs[64], aDs[64];
    int t = threadIdx.x;
    const float* __restrict__ Wt = (LAYER == 1) ? g_W2t : g_Wot;
    for (int i = t; i < 64 * 64; i += 256) Wts[(i >> 6) * INp + (i & 63)] = Wt[i];
    if (LAYER == 1 && t < 64) { aSs[t] = attS[t]; aDs[t] = attD[t]; }

    // ---- gather phase ----
    int grp = t >> 4, gl = t & 15;
    int nb0 = blockIdx.x * 16;
    int n = nb0 + grp;
    int h = gl >> 2;
    const float* __restrict__ aSrc = (LAYER == 1) ? g_asrc : g_asrc2;
    const float* __restrict__ aDst = (LAYER == 1) ? g_adst : g_adst2;
    const float* __restrict__ aeL = (LAYER == 1) ? g_ae1 : g_ae2;
    const float4* __restrict__ xp4 =
        (const float4*)((LAYER == 1) ? g_xp : g_xp2);
    float aD = aDst[n * 4 + h];
    int p = g_off[n], pend = g_cur[n];
    float4 acc = make_float4(0.f, 0.f, 0.f, 0.f);
    float den = 0.f;
#pragma unroll 4
    for (; p < pend; p++) {
        int2 se = g_el2[p];
        float a = aSrc[se.x * 4 + h] + aD + aeL[(size_t)se.y * 4 + h];
        a = a > 0.f ? a : 0.2f * a;
        float w = __expf(a);
        float4 v = xp4[se.x * 16 + gl];
        acc.x += w * v.x;
        acc.y += w * v.y;
        acc.z += w * v.z;
        acc.w += w * v.w;
        den += w;
    }
    float inv = 1.f / fmaxf(den, 1e-16f);
    *(float4*)&xs[grp * INp + gl * 4] =
        make_float4(fmaxf(acc.x * inv, 0.f), fmaxf(acc.y * inv, 0.f),
                    fmaxf(acc.z * inv, 0.f), fmaxf(acc.w * inv, 0.f));
    __syncthreads();

    // ---- GEMM phase ----
    int c = t & 63, q = t >> 6;
    const float* wr = &Wts[c * INp];
    const float* x0 = &xs[(q * 4 + 0) * INp];
    const float* x1 = &xs[(q * 4 + 1) * INp];
    const float* x2 = &xs[(q * 4 + 2) * INp];
    const float* x3 = &xs[(q * 4 + 3) * INp];
    u64 p0 = 0ull, p1 = 0ull, p2 = 0ull, p3 = 0ull;
#pragma unroll
    for (int k = 0; k < 64; k += 4) {
        ulonglong2 w  = *(const ulonglong2*)&wr[k];
        ulonglong2 u0 = *(const ulonglong2*)&x0[k];
        ulonglong2 u1 = *(const ulonglong2*)&x1[k];
        ulonglong2 u2 = *(const ulonglong2*)&x2[k];
        ulonglong2 u3 = *(const ulonglong2*)&x3[k];
        p0 = ffma2(w.x, u0.x, p0); p0 = ffma2(w.y, u0.y, p0);
        p1 = ffma2(w.x, u1.x, p1); p1 = ffma2(w.y, u1.y, p1);
        p2 = ffma2(w.x, u2.x, p2); p2 = ffma2(w.y, u2.y, p2);
        p3 = ffma2(w.x, u3.x, p3); p3 = ffma2(w.y, u3.y, p3);
    }
    float a0 = hsum2(p0), a1 = hsum2(p1), a2 = hsum2(p2), a3 = hsum2(p3);
    int nb = nb0 + q * 4;
    if (LAYER == 2) {
        float b = bias[c];
        outp[(size_t)(nb + 0) * 64 + c] = a0 + b;
        outp[(size_t)(nb + 1) * 64 + c] = a1 + b;
        outp[(size_t)(nb + 2) * 64 + c] = a2 + b;
        outp[(size_t)(nb + 3) * 64 + c] = a3 + b;
    } else {
        float aS = aSs[c], aDv = aDs[c];
        int lane = t & 31, head = c >> 4;
        float av[4] = {a0, a1, a2, a3};
#pragma unroll
        for (int j = 0; j < 4; j++) {
            g_xp2[(size_t)(nb + j) * 64 + c] = av[j];
            float r1 = av[j] * aS;
            float r2 = av[j] * aDv;
#pragma unroll
            for (int o = 8; o; o >>= 1) {
                r1 += __shfl_xor_sync(0xffffffffu, r1, o);
                r2 += __shfl_xor_sync(0xffffffffu, r2, o);
            }
            if ((lane & 15) == 0) {
                g_asrc2[(nb + j) * 4 + head] = r1;
                g_adst2[(nb + j) * 4 + head] = r2;
            }
        }
    }
}

// ---------------------------------------------------------------------------
extern "C" void kernel_launch(void* const* d_in, const int* in_sizes, int n_in,
                              void* d_out, int out_size) {
    const float* x = (const float*)d_in[0];
    const int* ei = (const int*)d_in[1];
    const float* edge_attr = (const float*)d_in[2];
    const float* W1 = (const float*)d_in[3];
    const float* We1 = (const float*)d_in[4];
    const float* as1 = (const float*)d_in[5];
    const float* ad1 = (const float*)d_in[6];
    const float* ae1 = (const float*)d_in[7];
    const float* W2 = (const float*)d_in[8];
    const float* We2 = (const float*)d_in[9];
    const float* as2 = (const float*)d_in[10];
    const float* ad2 = (const float*)d_in[11];
    const float* ae2 = (const float*)d_in[12];
    const float* Wout = (const float*)d_in[13];
    const float* bout = (const float*)d_in[14];
    float* out = (float*)d_out;

    // 1: zero cnt/total + P fold + weight transpose
    setup_kernel<<<NBLK1 + 1 + 32, 256>>>(We1, We2, ae1, ae2, W1, W2, Wout);
    // 2-4: CSR build (histogram -> bump alloc -> fill)
    hist_kernel<<<EE / 256, 256>>>(ei);
    alloc_kernel<<<NBLK1, 256>>>();
    fill_kernel<<<EE / 256, 256>>>(ei);
    // 5: big fused kernel (ae stream + layer-1 node GEMM)
    fused_ae_node0_kernel<<<AE_BLOCKS + N0_BLOCKS, 256>>>(edge_attr, x, as1, ad1);
    // 6: gather layer 1 + layer-2 node GEMM (writes xp2/att2)
    gather_node_kernel<1><<<NN / 16, 256>>>(as2, ad2, nullptr, nullptr);
    // 7: gather layer 2 + output GEMM
    gather_node_kernel<2><<<NN / 16, 256>>>(nullptr, nullptr, bout, out);
}